// round 5
// baseline (speedup 1.0000x reference)
#include <cuda_runtime.h>
#include <cuda_bf16.h>
#include <cstdint>
#include <cstddef>

// Problem constants
#define C_IN   256
#define C_OUT  256
#define KPTS   15
#define NNB    16
#define HH     64
#define WW     2048
#define KP_EXT 1.2f
#define BN_EPS 1e-5f
#define MAXB   8
#define MAXN   40000
#define KD     (KPTS * C_IN)        // 3840

// ---------------- scratch (device globals) ----------------
__device__ int   g_cum[MAXB + 1];
__device__ float g_feats[(size_t)MAXN * C_IN];
__device__ __nv_bfloat16 g_Ahi[(size_t)MAXN * KD];     // 307 MB
__device__ __nv_bfloat16 g_Alo[(size_t)MAXN * KD];     // 307 MB
__device__ __nv_bfloat16 g_Bhi[(size_t)C_OUT * KD];    // 1.9 MB, K-major [d][kc]
__device__ __nv_bfloat16 g_Blo[(size_t)C_OUT * KD];
__device__ float g_psum[256 * C_OUT];
__device__ float g_psq[256 * C_OUT];
__device__ float g_scale[C_OUT];
__device__ float g_bias[C_OUT];

// ---------------- PTX helpers (base sm_103-legal only) ----------------
__device__ __forceinline__ uint32_t smem_u32(const void* p) {
    uint32_t a;
    asm("{ .reg .u64 t; cvta.to.shared.u64 t, %1; cvt.u32.u64 %0, t; }" : "=r"(a) : "l"(p));
    return a;
}

#define CP_ASYNC16(dst_u32, src_ptr) \
    asm volatile("cp.async.cg.shared.global [%0], [%1], 16;" \
                 :: "r"(dst_u32), "l"(src_ptr) : "memory")
#define CP_COMMIT() asm volatile("cp.async.commit_group;" ::: "memory")
#define CP_WAIT1()  asm volatile("cp.async.wait_group 1;" ::: "memory")
#define CP_WAIT0()  asm volatile("cp.async.wait_group 0;" ::: "memory")

__device__ __forceinline__ void ldsm4(uint32_t* r, uint32_t addr) {
    asm volatile("ldmatrix.sync.aligned.m8n8.x4.shared.b16 {%0,%1,%2,%3}, [%4];"
                 : "=r"(r[0]), "=r"(r[1]), "=r"(r[2]), "=r"(r[3]) : "r"(addr));
}

__device__ __forceinline__ void mma16816(float* c, const uint32_t* a,
                                         uint32_t b0, uint32_t b1) {
    asm volatile(
        "mma.sync.aligned.m16n8k16.row.col.f32.bf16.bf16.f32 "
        "{%0,%1,%2,%3}, {%4,%5,%6,%7}, {%8,%9}, {%0,%1,%2,%3};"
        : "+f"(c[0]), "+f"(c[1]), "+f"(c[2]), "+f"(c[3])
        : "r"(a[0]), "r"(a[1]), "r"(a[2]), "r"(a[3]), "r"(b0), "r"(b1));
}

__device__ __forceinline__ int batch_of(int n, int Bn) {
    int b = 0;
#pragma unroll
    for (int i = 1; i < MAXB; i++)
        if (i < Bn && n >= g_cum[i]) b = i;
    return b;
}

// ---------------- kernel 0: prefix sums ----------------
__global__ void prep_kernel(const int* __restrict__ np, int Bn) {
    if (threadIdx.x == 0 && blockIdx.x == 0) {
        int c = 0;
        for (int b = 0; b < Bn && b < MAXB; b++) { g_cum[b] = c; c += np[b]; }
        for (int b = Bn; b < MAXB; b++) g_cum[b] = c;
        g_cum[MAXB] = c;
    }
}

// ---------------- kernel 0b: B hi/lo transpose  B[d, kc] = kpw[kc, d] ----------------
__global__ void bprep_kernel(const float* __restrict__ kpw) {
    int i = blockIdx.x * blockDim.x + threadIdx.x;
    if (i >= KD * C_OUT) return;
    int kc = i >> 8;
    int d  = i & 255;
    float v = kpw[i];
    __nv_bfloat16 h = __float2bfloat16(v);
    float rem = v - __bfloat162float(h);
    g_Bhi[(size_t)d * KD + kc] = h;
    g_Blo[(size_t)d * KD + kc] = __float2bfloat16(rem);
}

// ---------------- kernel 1: bilinear grid sample ----------------
__global__ void feats_kernel(const float* __restrict__ x,
                             const float* __restrict__ px,
                             const float* __restrict__ py,
                             int N, int Bn) {
    int n = blockIdx.x;
    int c = threadIdx.x;
    if (n >= N) return;
    int b = batch_of(n, Bn);

    float ix = fminf(fmaxf((px[n] + 1.0f) * (WW * 0.5f) - 0.5f, 0.0f), (float)(WW - 1));
    float iy = fminf(fmaxf((py[n] + 1.0f) * (HH * 0.5f) - 0.5f, 0.0f), (float)(HH - 1));
    float x0f = floorf(ix), y0f = floorf(iy);
    float wx = ix - x0f, wy = iy - y0f;
    int x0 = (int)x0f, y0 = (int)y0f;
    int x1 = min(x0 + 1, WW - 1);
    int y1 = min(y0 + 1, HH - 1);

    const float* base = x + ((size_t)b * C_IN + c) * (size_t)(HH * WW);
    float v00 = base[(size_t)y0 * WW + x0];
    float v01 = base[(size_t)y0 * WW + x1];
    float v10 = base[(size_t)y1 * WW + x0];
    float v11 = base[(size_t)y1 * WW + x1];

    float top = v00 + (v01 - v00) * wx;
    float bot = v10 + (v11 - v10) * wx;
    g_feats[(size_t)n * C_IN + c] = top + (bot - top) * wy;
}

// ---------------- kernel 3: fused kp-weights + weighted -> bf16 hi/lo ----------------
// block = one point, 256 threads
__global__ void weighted_kernel(const float* __restrict__ pxyz,
                                const int* __restrict__ pknn,
                                const float* __restrict__ kp,
                                int N, int Bn) {
    int n = blockIdx.x;
    int c = threadIdx.x;
    if (n >= N) return;

    __shared__ float skp[KPTS * 3];
    __shared__ float sw[NNB * KPTS];   // [a][k]
    __shared__ int sidx[NNB];

    if (c < KPTS * 3) skp[c] = kp[c];
    if (c < NNB) {
        int b = batch_of(n, Bn);
        sidx[c] = pknn[(size_t)n * NNB + c] + g_cum[b];
    }
    __syncthreads();

    if (c < NNB * KPTS) {
        int a = c & 15;      // neighbor
        int k = c >> 4;      // kernel point (0..14)
        int j = sidx[a];
        float rx = pxyz[(size_t)j * 3 + 0] - pxyz[(size_t)n * 3 + 0];
        float ry = pxyz[(size_t)j * 3 + 1] - pxyz[(size_t)n * 3 + 1];
        float rz = pxyz[(size_t)j * 3 + 2] - pxyz[(size_t)n * 3 + 2];
        float dx = rx - skp[k * 3 + 0];
        float dy = ry - skp[k * 3 + 1];
        float dz = rz - skp[k * 3 + 2];
        float dist = sqrtf(dx * dx + dy * dy + dz * dz);
        sw[a * KPTS + k] = fmaxf(1.0f - dist * (1.0f / KP_EXT), 0.0f);
    }
    __syncthreads();

    float nx[NNB];
#pragma unroll
    for (int a = 0; a < NNB; a++)
        nx[a] = g_feats[(size_t)sidx[a] * C_IN + c];

#pragma unroll
    for (int k = 0; k < KPTS; k++) {
        float acc = 0.0f;
#pragma unroll
        for (int a = 0; a < NNB; a++)
            acc = fmaf(sw[a * KPTS + k], nx[a], acc);
        __nv_bfloat16 h = __float2bfloat16(acc);
        float rem = acc - __bfloat162float(h);
        size_t idx = (size_t)n * KD + k * C_IN + c;
        g_Ahi[idx] = h;
        g_Alo[idx] = __float2bfloat16(rem);
    }
}

// ---------------- kernel 4: HMMA bf16 3-pass GEMM ----------------
// C[m, d] = sum_kc A[m,kc] * B[d,kc]
// CTA: 64(M) x 256(N full), 8 warps = 2(M) x 4(N), warp tile 32 x 64
#define GM 64
#define GN 256
#define KCHUNK 64
#define NCHUNKS (KD / KCHUNK)           // 60
#define OFF_AH 0
#define OFF_AL 8192
#define OFF_BH 16384
#define OFF_BL 49152
#define STAGE_BYTES 81920               // 80 KB
#define GEMM_SMEM (2 * STAGE_BYTES + 1024)

extern __shared__ char gemm_smem[];

__device__ __forceinline__ void issue_chunk(uint32_t stage_u32, int mBase,
                                            int k0, int M, int tid) {
    int r_lo = tid >> 3;        // 0..31
    int i    = tid & 7;         // 16B granule within 128B row
#pragma unroll
    for (int p = 0; p < 2; p++) {           // Ah: rows 0..63
        int row = p * 32 + r_lo;
        uint32_t off = (uint32_t)(row * 128 + i * 16);
        uint32_t sw = off ^ ((off >> 3) & 0x70);
        int gr = min(mBase + row, M - 1);
        CP_ASYNC16(stage_u32 + OFF_AH + sw, g_Ahi + (size_t)gr * KD + k0 + i * 8);
    }
#pragma unroll
    for (int p = 0; p < 2; p++) {           // Al
        int row = p * 32 + r_lo;
        uint32_t off = (uint32_t)(row * 128 + i * 16);
        uint32_t sw = off ^ ((off >> 3) & 0x70);
        int gr = min(mBase + row, M - 1);
        CP_ASYNC16(stage_u32 + OFF_AL + sw, g_Alo + (size_t)gr * KD + k0 + i * 8);
    }
#pragma unroll
    for (int p = 0; p < 8; p++) {           // Bh: rows 0..255
        int row = p * 32 + r_lo;
        uint32_t off = (uint32_t)(row * 128 + i * 16);
        uint32_t sw = off ^ ((off >> 3) & 0x70);
        CP_ASYNC16(stage_u32 + OFF_BH + sw, g_Bhi + (size_t)row * KD + k0 + i * 8);
    }
#pragma unroll
    for (int p = 0; p < 8; p++) {           // Bl
        int row = p * 32 + r_lo;
        uint32_t off = (uint32_t)(row * 128 + i * 16);
        uint32_t sw = off ^ ((off >> 3) & 0x70);
        CP_ASYNC16(stage_u32 + OFF_BL + sw, g_Blo + (size_t)row * KD + k0 + i * 8);
    }
}

__global__ void __launch_bounds__(256, 1) gemm_mma_kernel(float* __restrict__ C, int M) {
    int tid = threadIdx.x;
    int wid = tid >> 5;
    int lane = tid & 31;
    int wm = wid & 1;          // 0..1  (32 rows each)
    int wn = wid >> 1;         // 0..3  (64 cols each)
    int mBase = blockIdx.x * GM;

    uint32_t dyn_u32 = smem_u32(gemm_smem);
    uint32_t base_u32 = (dyn_u32 + 1023u) & ~1023u;

    float acc[2][8][4];
#pragma unroll
    for (int a = 0; a < 2; a++)
#pragma unroll
        for (int b = 0; b < 8; b++)
#pragma unroll
            for (int c = 0; c < 4; c++) acc[a][b][c] = 0.0f;

    int lrow = lane & 15;
    int csel = (lane >> 4) * 16;
    int aRow = wm * 32 + lrow;
    int bRow = wn * 64 + lrow;
    uint32_t xa = (uint32_t)((aRow & 7) << 4);
    uint32_t xb = (uint32_t)((bRow & 7) << 4);

    issue_chunk(base_u32, mBase, 0, M, tid);
    CP_COMMIT();

    for (int ch = 0; ch < NCHUNKS; ch++) {
        int buf = ch & 1;
        uint32_t stg = base_u32 + buf * STAGE_BYTES;

        if (ch + 1 < NCHUNKS) {
            issue_chunk(base_u32 + ((ch + 1) & 1) * STAGE_BYTES,
                        mBase, (ch + 1) * KCHUNK, M, tid);
            CP_COMMIT();
            CP_WAIT1();
        } else {
            CP_WAIT0();
        }
        __syncthreads();

        uint32_t aBase = stg + (uint32_t)(aRow * 128);
        uint32_t bBase = stg + (uint32_t)(bRow * 128);

#pragma unroll
        for (int ks = 0; ks < 4; ks++) {
            uint32_t colA = ((uint32_t)(ks * 32 + csel)) ^ xa;
            uint32_t colB = ((uint32_t)(ks * 32 + csel)) ^ xb;

            uint32_t ah[2][4], al[2][4];
#pragma unroll
            for (int mt = 0; mt < 2; mt++) {
                uint32_t addr = aBase + (uint32_t)(mt * 16 * 128) + colA;
                ldsm4(ah[mt], addr + OFF_AH);
                ldsm4(al[mt], addr + OFF_AL);
            }
            uint32_t bh[4][4], bl[4][4];
#pragma unroll
            for (int g = 0; g < 4; g++) {
                uint32_t addr = bBase + (uint32_t)(g * 16 * 128) + colB;
                ldsm4(bh[g], addr + OFF_BH);
                ldsm4(bl[g], addr + OFF_BL);
            }
#pragma unroll
            for (int mt = 0; mt < 2; mt++) {
#pragma unroll
                for (int nt = 0; nt < 8; nt++) {
                    int g = nt >> 1, h = nt & 1;
                    mma16816(acc[mt][nt], ah[mt], bh[g][h], bh[g][h + 2]);
                    mma16816(acc[mt][nt], ah[mt], bl[g][h], bl[g][h + 2]);
                    mma16816(acc[mt][nt], al[mt], bh[g][h], bh[g][h + 2]);
                }
            }
        }
        __syncthreads();
    }

    // epilogue: m16n8 accumulator mapping
    int rBase = mBase + wm * 32 + (lane >> 2);
    int cBase = wn * 64 + (lane & 3) * 2;
#pragma unroll
    for (int mt = 0; mt < 2; mt++) {
#pragma unroll
        for (int nt = 0; nt < 8; nt++) {
            int r0 = rBase + mt * 16;
            int cc = cBase + nt * 8;
            if (r0 < M)
                *(float2*)(C + (size_t)r0 * C_OUT + cc) =
                    make_float2(acc[mt][nt][0], acc[mt][nt][1]);
            if (r0 + 8 < M)
                *(float2*)(C + (size_t)(r0 + 8) * C_OUT + cc) =
                    make_float2(acc[mt][nt][2], acc[mt][nt][3]);
        }
    }
}

// ---------------- kernel 5a/5b: BN stats (deterministic two-pass) ----------------
__global__ void colstats_partial(const float* __restrict__ out0, int N) {
    int d = threadIdx.x;
    int blk = blockIdx.x;
    float s = 0.f, ss = 0.f;
    for (int r = blk; r < N; r += gridDim.x) {
        float v = out0[(size_t)r * C_OUT + d];
        s += v;
        ss += v * v;
    }
    g_psum[blk * C_OUT + d] = s;
    g_psq[blk * C_OUT + d]  = ss;
}

__global__ void colstats_final(const float* __restrict__ gamma,
                               const float* __restrict__ beta,
                               int N, int nchunks) {
    int d = threadIdx.x;
    float s = 0.f, ss = 0.f;
    for (int i = 0; i < nchunks; i++) {
        s += g_psum[i * C_OUT + d];
        ss += g_psq[i * C_OUT + d];
    }
    float invN = 1.0f / (float)N;
    float mean = s * invN;
    float var = ss * invN - mean * mean;
    float sc = rsqrtf(var + BN_EPS) * gamma[d];
    g_scale[d] = sc;
    g_bias[d] = beta[d] - mean * sc;
}

// ---------------- kernel 6: BN + ReLU ----------------
__global__ void bn_relu_kernel(float* __restrict__ out, size_t total) {
    for (size_t i = (size_t)blockIdx.x * blockDim.x + threadIdx.x; i < total;
         i += (size_t)gridDim.x * blockDim.x) {
        int d = (int)(i & (C_OUT - 1));
        float v = fmaf(out[i], g_scale[d], g_bias[d]);
        out[i] = v > 0.0f ? v : 0.0f;
    }
}

// ---------------- launch ----------------
extern "C" void kernel_launch(void* const* d_in, const int* in_sizes, int n_in,
                              void* d_out, int out_size) {
    const float* x     = (const float*)d_in[0];
    const float* px    = (const float*)d_in[1];
    const float* py    = (const float*)d_in[2];
    const float* pxyz  = (const float*)d_in[3];
    const int*   pknn  = (const int*)d_in[4];
    const int*   np    = (const int*)d_in[5];
    const float* kp    = (const float*)d_in[6];
    const float* kpw   = (const float*)d_in[7];
    const float* gamma = (const float*)d_in[8];
    const float* beta  = (const float*)d_in[9];
    float* out = (float*)d_out;

    int N  = in_sizes[1];
    int Bn = in_sizes[5];

    cudaFuncSetAttribute(gemm_mma_kernel,
                         cudaFuncAttributeMaxDynamicSharedMemorySize, GEMM_SMEM);

    prep_kernel<<<1, 32>>>(np, Bn);
    bprep_kernel<<<(KD * C_OUT + 255) / 256, 256>>>(kpw);
    feats_kernel<<<N, C_IN>>>(x, px, py, N, Bn);

    weighted_kernel<<<N, C_IN>>>(pxyz, pknn, kp, N, Bn);

    int nblk = (N + GM - 1) / GM;
    gemm_mma_kernel<<<nblk, 256, GEMM_SMEM>>>(out, N);

    colstats_partial<<<256, C_OUT>>>(out, N);
    colstats_final<<<1, C_OUT>>>(gamma, beta, N, 256);

    size_t total = (size_t)N * C_OUT;
    bn_relu_kernel<<<2048, 256>>>(out, total);
}

// round 6
// speedup vs baseline: 1.4018x; 1.4018x over previous
#include <cuda_runtime.h>
#include <cuda_bf16.h>
#include <cstdint>
#include <cstddef>

// Problem constants
#define C_IN   256
#define C_OUT  256
#define KPTS   15
#define NNB    16
#define HH     64
#define WW     2048
#define KP_EXT 1.2f
#define BN_EPS 1e-5f
#define MAXB   8
#define MAXN   40000
#define KD     (KPTS * C_IN)        // 3840

// ---------------- scratch (device globals) ----------------
__device__ int   g_cum[MAXB + 1];
__device__ float g_feats[(size_t)MAXN * C_IN];
__device__ float g_allw[(size_t)MAXN * NNB * KPTS];
__device__ __nv_bfloat16 g_Ahi[(size_t)MAXN * KD];     // 307 MB
__device__ __nv_bfloat16 g_Alo[(size_t)MAXN * KD];     // 307 MB
__device__ __nv_bfloat16 g_Bhi[(size_t)C_OUT * KD];    // 1.9 MB, K-major [d][kc]
__device__ __nv_bfloat16 g_Blo[(size_t)C_OUT * KD];
__device__ float g_psum[256 * C_OUT];
__device__ float g_psq[256 * C_OUT];
__device__ float g_scale[C_OUT];
__device__ float g_bias[C_OUT];

// ---------------- PTX helpers (base sm_103-legal only) ----------------
__device__ __forceinline__ uint32_t smem_u32(const void* p) {
    uint32_t a;
    asm("{ .reg .u64 t; cvta.to.shared.u64 t, %1; cvt.u32.u64 %0, t; }" : "=r"(a) : "l"(p));
    return a;
}

#define CP_ASYNC16(dst_u32, src_ptr) \
    asm volatile("cp.async.cg.shared.global [%0], [%1], 16;" \
                 :: "r"(dst_u32), "l"(src_ptr) : "memory")
#define CP_COMMIT() asm volatile("cp.async.commit_group;" ::: "memory")
#define CP_WAIT2()  asm volatile("cp.async.wait_group 2;" ::: "memory")
#define CP_WAIT1()  asm volatile("cp.async.wait_group 1;" ::: "memory")
#define CP_WAIT0()  asm volatile("cp.async.wait_group 0;" ::: "memory")

__device__ __forceinline__ void ldsm4(uint32_t* r, uint32_t addr) {
    asm volatile("ldmatrix.sync.aligned.m8n8.x4.shared.b16 {%0,%1,%2,%3}, [%4];"
                 : "=r"(r[0]), "=r"(r[1]), "=r"(r[2]), "=r"(r[3]) : "r"(addr));
}

__device__ __forceinline__ void mma16816(float* c, const uint32_t* a,
                                         uint32_t b0, uint32_t b1) {
    asm volatile(
        "mma.sync.aligned.m16n8k16.row.col.f32.bf16.bf16.f32 "
        "{%0,%1,%2,%3}, {%4,%5,%6,%7}, {%8,%9}, {%0,%1,%2,%3};"
        : "+f"(c[0]), "+f"(c[1]), "+f"(c[2]), "+f"(c[3])
        : "r"(a[0]), "r"(a[1]), "r"(a[2]), "r"(a[3]), "r"(b0), "r"(b1));
}

__device__ __forceinline__ int batch_of(int n, int Bn) {
    int b = 0;
#pragma unroll
    for (int i = 1; i < MAXB; i++)
        if (i < Bn && n >= g_cum[i]) b = i;
    return b;
}

// ---------------- kernel 0: prefix sums ----------------
__global__ void prep_kernel(const int* __restrict__ np, int Bn) {
    if (threadIdx.x == 0 && blockIdx.x == 0) {
        int c = 0;
        for (int b = 0; b < Bn && b < MAXB; b++) { g_cum[b] = c; c += np[b]; }
        for (int b = Bn; b < MAXB; b++) g_cum[b] = c;
        g_cum[MAXB] = c;
    }
}

// ---------------- kernel 0b: B hi/lo transpose  B[d, kc] = kpw[kc, d] ----------------
__global__ void bprep_kernel(const float* __restrict__ kpw) {
    int i = blockIdx.x * blockDim.x + threadIdx.x;
    if (i >= KD * C_OUT) return;
    int kc = i >> 8;
    int d  = i & 255;
    float v = kpw[i];
    __nv_bfloat16 h = __float2bfloat16(v);
    float rem = v - __bfloat162float(h);
    g_Bhi[(size_t)d * KD + kc] = h;
    g_Blo[(size_t)d * KD + kc] = __float2bfloat16(rem);
}

// ---------------- kernel 1: bilinear grid sample ----------------
__global__ void feats_kernel(const float* __restrict__ x,
                             const float* __restrict__ px,
                             const float* __restrict__ py,
                             int N, int Bn) {
    int n = blockIdx.x;
    int c = threadIdx.x;
    if (n >= N) return;
    int b = batch_of(n, Bn);

    float ix = fminf(fmaxf((px[n] + 1.0f) * (WW * 0.5f) - 0.5f, 0.0f), (float)(WW - 1));
    float iy = fminf(fmaxf((py[n] + 1.0f) * (HH * 0.5f) - 0.5f, 0.0f), (float)(HH - 1));
    float x0f = floorf(ix), y0f = floorf(iy);
    float wx = ix - x0f, wy = iy - y0f;
    int x0 = (int)x0f, y0 = (int)y0f;
    int x1 = min(x0 + 1, WW - 1);
    int y1 = min(y0 + 1, HH - 1);

    const float* base = x + ((size_t)b * C_IN + c) * (size_t)(HH * WW);
    float v00 = base[(size_t)y0 * WW + x0];
    float v01 = base[(size_t)y0 * WW + x1];
    float v10 = base[(size_t)y1 * WW + x0];
    float v11 = base[(size_t)y1 * WW + x1];

    float top = v00 + (v01 - v00) * wx;
    float bot = v10 + (v11 - v10) * wx;
    g_feats[(size_t)n * C_IN + c] = top + (bot - top) * wy;
}

// ---------------- kernel 2: kernel-point weights ----------------
__global__ void allw_kernel(const float* __restrict__ pxyz,
                            const int* __restrict__ pknn,
                            const float* __restrict__ kp,
                            int N, int Bn) {
    __shared__ float skp[KPTS * 3];
    if (threadIdx.x < KPTS * 3) skp[threadIdx.x] = kp[threadIdx.x];
    __syncthreads();

    int t = blockIdx.x * blockDim.x + threadIdx.x;
    int n = t / NNB;
    int a = t % NNB;
    if (n >= N) return;
    int b = batch_of(n, Bn);
    int j = pknn[(size_t)n * NNB + a] + g_cum[b];

    float cx = pxyz[(size_t)n * 3 + 0];
    float cy = pxyz[(size_t)n * 3 + 1];
    float cz = pxyz[(size_t)n * 3 + 2];
    float rx = pxyz[(size_t)j * 3 + 0] - cx;
    float ry = pxyz[(size_t)j * 3 + 1] - cy;
    float rz = pxyz[(size_t)j * 3 + 2] - cz;

#pragma unroll
    for (int k = 0; k < KPTS; k++) {
        float dx = rx - skp[k * 3 + 0];
        float dy = ry - skp[k * 3 + 1];
        float dz = rz - skp[k * 3 + 2];
        float dist = sqrtf(dx * dx + dy * dy + dz * dz);
        g_allw[((size_t)n * NNB + a) * KPTS + k] = fmaxf(1.0f - dist * (1.0f / KP_EXT), 0.0f);
    }
}

// ---------------- kernel 3: weighted -> bf16 hi/lo split ----------------
__global__ void __launch_bounds__(256, 3)
weighted_kernel(const int* __restrict__ pknn, int N, int Bn) {
    int n = blockIdx.x;
    int c = threadIdx.x;
    if (n >= N) return;

    __shared__ float sw[NNB * KPTS];
    __shared__ int sidx[NNB];
    if (c < NNB) {
        int b = batch_of(n, Bn);
        sidx[c] = pknn[(size_t)n * NNB + c] + g_cum[b];
    }
    if (c < NNB * KPTS) sw[c] = g_allw[(size_t)n * NNB * KPTS + c];
    __syncthreads();

    float nx[NNB];
#pragma unroll
    for (int a = 0; a < NNB; a++)
        nx[a] = g_feats[(size_t)sidx[a] * C_IN + c];

#pragma unroll
    for (int k = 0; k < KPTS; k++) {
        float acc = 0.0f;
#pragma unroll
        for (int a = 0; a < NNB; a++)
            acc = fmaf(sw[a * KPTS + k], nx[a], acc);
        __nv_bfloat16 h = __float2bfloat16(acc);
        float rem = acc - __bfloat162float(h);
        size_t idx = (size_t)n * KD + k * C_IN + c;
        g_Ahi[idx] = h;
        g_Alo[idx] = __float2bfloat16(rem);
    }
}

// ---------------- kernel 4: HMMA bf16 3-pass GEMM (3-stage cp.async pipeline) ----------------
// C[m, d] = sum_kc A[m,kc] * B[d,kc]
// CTA: 128(M) x 128(N), 8 warps = 2(M) x 4(N), warp tile 64 x 32
#define GM 128
#define GN 128
#define KCHUNK 64
#define NCHUNKS (KD / KCHUNK)           // 60
#define ARR_BYTES 16384                 // one 128x64 bf16 array
#define OFF_AH 0
#define OFF_AL 16384
#define OFF_BH 32768
#define OFF_BL 49152
#define STAGE_BYTES 65536
#define NSTAGE 3
#define GEMM_SMEM (NSTAGE * STAGE_BYTES + 1024)

extern __shared__ char gemm_smem[];

__device__ __forceinline__ void issue_chunk(uint32_t stage_u32, int mBase, int nBase,
                                            int k0, int M, int tid) {
    int r_lo = tid >> 3;        // 0..31
    int i    = tid & 7;         // 16B granule within 128B row
    const __nv_bfloat16* __restrict__ Ah = g_Ahi;
    const __nv_bfloat16* __restrict__ Al = g_Alo;
    const __nv_bfloat16* __restrict__ Bh = g_Bhi;
    const __nv_bfloat16* __restrict__ Bl = g_Blo;
#pragma unroll
    for (int p = 0; p < 16; p++) {
        int quarter = p >> 2;                   // 0:Ah 1:Al 2:Bh 3:Bl
        int row = ((p & 3) * 32 + r_lo) & 127;  // 0..127
        uint32_t off = (uint32_t)(row * 128 + i * 16);
        uint32_t sw = off ^ ((off >> 3) & 0x70);
        uint32_t dst = stage_u32 + quarter * ARR_BYTES + sw;
        const __nv_bfloat16* src;
        if (quarter == 0) {
            int gr = min(mBase + row, M - 1);
            src = Ah + (size_t)gr * KD + k0 + i * 8;
        } else if (quarter == 1) {
            int gr = min(mBase + row, M - 1);
            src = Al + (size_t)gr * KD + k0 + i * 8;
        } else if (quarter == 2) {
            src = Bh + (size_t)(nBase + row) * KD + k0 + i * 8;
        } else {
            src = Bl + (size_t)(nBase + row) * KD + k0 + i * 8;
        }
        CP_ASYNC16(dst, src);
    }
}

__global__ void __launch_bounds__(256, 1) gemm_mma_kernel(float* __restrict__ C, int M) {
    int tid = threadIdx.x;
    int wid = tid >> 5;
    int lane = tid & 31;
    int wm = wid & 1;          // 0..1  (64 rows each)
    int wn = wid >> 1;         // 0..3  (32 cols each)
    int mBase = blockIdx.y * GM;
    int nBase = blockIdx.x * GN;

    uint32_t dyn_u32 = smem_u32(gemm_smem);
    uint32_t base_u32 = (dyn_u32 + 1023u) & ~1023u;

    float acc[4][4][4];
#pragma unroll
    for (int a = 0; a < 4; a++)
#pragma unroll
        for (int b = 0; b < 4; b++)
#pragma unroll
            for (int c = 0; c < 4; c++) acc[a][b][c] = 0.0f;

    // per-lane ldmatrix address components
    int lrow = lane & 15;                 // row within 16-row group
    int csel = (lane >> 4) * 16;          // 16B column half (k0-7 / k8-15)
    int aRow = wm * 64 + lrow;            // A row for mt=0
    int bRow = wn * 32 + lrow;            // B row for 16-n group 0
    uint32_t xa = (uint32_t)((aRow & 7) << 4);
    uint32_t xb = (uint32_t)((bRow & 7) << 4);

    // prologue: fill 2 of 3 stages
    issue_chunk(base_u32 + 0 * STAGE_BYTES, mBase, nBase, 0, M, tid);
    CP_COMMIT();
    issue_chunk(base_u32 + 1 * STAGE_BYTES, mBase, nBase, KCHUNK, M, tid);
    CP_COMMIT();

    int bufsel = 0;
    for (int ch = 0; ch < NCHUNKS; ch++) {
        uint32_t stg = base_u32 + bufsel * STAGE_BYTES;

        if (ch + 2 < NCHUNKS) {
            int nbuf = bufsel + 2; if (nbuf >= NSTAGE) nbuf -= NSTAGE;
            issue_chunk(base_u32 + nbuf * STAGE_BYTES,
                        mBase, nBase, (ch + 2) * KCHUNK, M, tid);
            CP_COMMIT();
            CP_WAIT2();
        } else if (ch + 1 < NCHUNKS) {
            CP_WAIT1();
        } else {
            CP_WAIT0();
        }
        __syncthreads();

        uint32_t aBase = stg + (uint32_t)(aRow * 128);
        uint32_t bBase = stg + (uint32_t)(bRow * 128);

#pragma unroll
        for (int ks = 0; ks < 4; ks++) {
            uint32_t colA = ((uint32_t)(ks * 32 + csel)) ^ xa;
            uint32_t colB = ((uint32_t)(ks * 32 + csel)) ^ xb;

            uint32_t ah[4][4], al[4][4];
#pragma unroll
            for (int mt = 0; mt < 4; mt++) {
                uint32_t addr = aBase + (uint32_t)(mt * 16 * 128) + colA;
                ldsm4(ah[mt], addr + OFF_AH);
                ldsm4(al[mt], addr + OFF_AL);
            }
            uint32_t bh[2][4], bl[2][4];
#pragma unroll
            for (int g = 0; g < 2; g++) {
                uint32_t addr = bBase + (uint32_t)(g * 16 * 128) + colB;
                ldsm4(bh[g], addr + OFF_BH);
                ldsm4(bl[g], addr + OFF_BL);
            }
#pragma unroll
            for (int mt = 0; mt < 4; mt++) {
#pragma unroll
                for (int nt = 0; nt < 4; nt++) {
                    int g = nt >> 1, h = nt & 1;
                    mma16816(acc[mt][nt], ah[mt], bh[g][h], bh[g][h + 2]);
                    mma16816(acc[mt][nt], ah[mt], bl[g][h], bl[g][h + 2]);
                    mma16816(acc[mt][nt], al[mt], bh[g][h], bh[g][h + 2]);
                }
            }
        }
        __syncthreads();

        bufsel++; if (bufsel >= NSTAGE) bufsel = 0;
    }

    // epilogue: standard m16n8 accumulator mapping
    int rBase = mBase + wm * 64 + (lane >> 2);
    int cBase = nBase + wn * 32 + (lane & 3) * 2;
#pragma unroll
    for (int mt = 0; mt < 4; mt++) {
#pragma unroll
        for (int nt = 0; nt < 4; nt++) {
            int r0 = rBase + mt * 16;
            int cc = cBase + nt * 8;
            if (r0 < M)
                *(float2*)(C + (size_t)r0 * C_OUT + cc) =
                    make_float2(acc[mt][nt][0], acc[mt][nt][1]);
            if (r0 + 8 < M)
                *(float2*)(C + (size_t)(r0 + 8) * C_OUT + cc) =
                    make_float2(acc[mt][nt][2], acc[mt][nt][3]);
        }
    }
}

// ---------------- kernel 5a/5b: BN stats (deterministic two-pass) ----------------
__global__ void colstats_partial(const float* __restrict__ out0, int N) {
    int d = threadIdx.x;
    int blk = blockIdx.x;
    float s = 0.f, ss = 0.f;
    for (int r = blk; r < N; r += gridDim.x) {
        float v = out0[(size_t)r * C_OUT + d];
        s += v;
        ss += v * v;
    }
    g_psum[blk * C_OUT + d] = s;
    g_psq[blk * C_OUT + d]  = ss;
}

__global__ void colstats_final(const float* __restrict__ gamma,
                               const float* __restrict__ beta,
                               int N, int nchunks) {
    int d = threadIdx.x;
    float s = 0.f, ss = 0.f;
    for (int i = 0; i < nchunks; i++) {
        s += g_psum[i * C_OUT + d];
        ss += g_psq[i * C_OUT + d];
    }
    float invN = 1.0f / (float)N;
    float mean = s * invN;
    float var = ss * invN - mean * mean;
    float sc = rsqrtf(var + BN_EPS) * gamma[d];
    g_scale[d] = sc;
    g_bias[d] = beta[d] - mean * sc;
}

// ---------------- kernel 6: BN + ReLU ----------------
__global__ void bn_relu_kernel(float* __restrict__ out, size_t total) {
    for (size_t i = (size_t)blockIdx.x * blockDim.x + threadIdx.x; i < total;
         i += (size_t)gridDim.x * blockDim.x) {
        int d = (int)(i & (C_OUT - 1));
        float v = fmaf(out[i], g_scale[d], g_bias[d]);
        out[i] = v > 0.0f ? v : 0.0f;
    }
}

// ---------------- launch ----------------
extern "C" void kernel_launch(void* const* d_in, const int* in_sizes, int n_in,
                              void* d_out, int out_size) {
    const float* x     = (const float*)d_in[0];
    const float* px    = (const float*)d_in[1];
    const float* py    = (const float*)d_in[2];
    const float* pxyz  = (const float*)d_in[3];
    const int*   pknn  = (const int*)d_in[4];
    const int*   np    = (const int*)d_in[5];
    const float* kp    = (const float*)d_in[6];
    const float* kpw   = (const float*)d_in[7];
    const float* gamma = (const float*)d_in[8];
    const float* beta  = (const float*)d_in[9];
    float* out = (float*)d_out;

    int N  = in_sizes[1];
    int Bn = in_sizes[5];

    cudaFuncSetAttribute(gemm_mma_kernel,
                         cudaFuncAttributeMaxDynamicSharedMemorySize, GEMM_SMEM);

    prep_kernel<<<1, 32>>>(np, Bn);
    bprep_kernel<<<(KD * C_OUT + 255) / 256, 256>>>(kpw);
    feats_kernel<<<N, C_IN>>>(x, px, py, N, Bn);

    int tot_na = N * NNB;
    allw_kernel<<<(tot_na + 255) / 256, 256>>>(pxyz, pknn, kp, N, Bn);

    weighted_kernel<<<N, C_IN>>>(pknn, N, Bn);

    dim3 ggrid(C_OUT / GN, (N + GM - 1) / GM);
    gemm_mma_kernel<<<ggrid, 256, GEMM_SMEM>>>(out, N);

    colstats_partial<<<256, C_OUT>>>(out, N);
    colstats_final<<<1, C_OUT>>>(gamma, beta, N, 256);

    size_t total = (size_t)N * C_OUT;
    bn_relu_kernel<<<2048, 256>>>(out, total);
}